// round 17
// baseline (speedup 1.0000x reference)
#include <cuda_runtime.h>
#include <cuda_fp16.h>
#include <stdint.h>

// ---------------------------------------------------------------------------
#define BATCH   2
#define SEQ     2048
#define DMODEL  1024
#define NHEADS  16
#define HDIM    64
#define MROWS   4096
#define QKV_N   3072

// ---------------------------------------------------------------------------
// Scratch (__device__ globals) — everything single fp16
// ---------------------------------------------------------------------------
__device__ __half g_x [(size_t)MROWS * DMODEL];
__device__ __half g_wq[(size_t)QKV_N * DMODEL];
__device__ __half g_wo[(size_t)DMODEL * DMODEL];
__device__ __half g_qkv[(size_t)MROWS * QKV_N];
__device__ __half g_att[(size_t)MROWS * DMODEL];

// ---------------------------------------------------------------------------
// PTX helpers (all sm_80+ — safe on compute_103)
// ---------------------------------------------------------------------------
__device__ __forceinline__ uint32_t smem_u32(const void* p) {
    uint32_t a;
    asm("{ .reg .u64 t; cvta.to.shared.u64 t, %1; cvt.u32.u64 %0, t; }" : "=r"(a) : "l"(p));
    return a;
}
__device__ __forceinline__ void ldsm_x4(uint32_t* r, uint32_t addr) {
    asm volatile("ldmatrix.sync.aligned.m8n8.x4.shared.b16 {%0,%1,%2,%3}, [%4];"
                 : "=r"(r[0]), "=r"(r[1]), "=r"(r[2]), "=r"(r[3]) : "r"(addr));
}
__device__ __forceinline__ void ldsm_x4_t(uint32_t* r, uint32_t addr) {
    asm volatile("ldmatrix.sync.aligned.m8n8.x4.trans.shared.b16 {%0,%1,%2,%3}, [%4];"
                 : "=r"(r[0]), "=r"(r[1]), "=r"(r[2]), "=r"(r[3]) : "r"(addr));
}
__device__ __forceinline__ void mma16816(float* d, const uint32_t* a, const uint32_t* b) {
    asm volatile(
        "mma.sync.aligned.m16n8k16.row.col.f32.f16.f16.f32 "
        "{%0,%1,%2,%3}, {%4,%5,%6,%7}, {%8,%9}, {%0,%1,%2,%3};"
        : "+f"(d[0]), "+f"(d[1]), "+f"(d[2]), "+f"(d[3])
        : "r"(a[0]), "r"(a[1]), "r"(a[2]), "r"(a[3]), "r"(b[0]), "r"(b[1]));
}
__device__ __forceinline__ void cp16(uint32_t dst, const void* src) {
    asm volatile("cp.async.cg.shared.global [%0], [%1], 16;" :: "r"(dst), "l"(src));
}
#define CP_COMMIT() asm volatile("cp.async.commit_group;" ::: "memory")
#define CP_WAIT(n)  asm volatile("cp.async.wait_group %0;" :: "n"(n) : "memory")

__device__ __forceinline__ uint32_t pack_h2(float a, float b) {
    __half2 t = __floats2half2_rn(a, b);
    return *(uint32_t*)&t;
}
__device__ __forceinline__ uint32_t scale_h2(uint32_t v, __half2 s) {
    __half2 t = __hmul2(*(__half2*)&v, s);
    return *(uint32_t*)&t;
}

// ---------------------------------------------------------------------------
// merged convert: fp32 -> fp16, three tensors, one launch
// ---------------------------------------------------------------------------
#define NX4 (MROWS * DMODEL / 4)
#define NQ4 (QKV_N * DMODEL / 4)
#define NO4 (DMODEL * DMODEL / 4)

__global__ __launch_bounds__(256) void cvt_all(
    const float* __restrict__ x, const float* __restrict__ wq, const float* __restrict__ wo,
    __half* __restrict__ xo, __half* __restrict__ wqo, __half* __restrict__ woo)
{
    int i = blockIdx.x * 256 + threadIdx.x;
    const float* src; __half* dst; int j;
    if (i < NX4)            { src = x;  dst = xo;  j = i; }
    else if (i < NX4 + NQ4) { src = wq; dst = wqo; j = i - NX4; }
    else if (i < NX4 + NQ4 + NO4) { src = wo; dst = woo; j = i - NX4 - NQ4; }
    else return;

    float4 v = ((const float4*)src)[j];
    ((__half2*)dst)[2 * j]     = __floats2half2_rn(v.x, v.y);
    ((__half2*)dst)[2 * j + 1] = __floats2half2_rn(v.z, v.w);
}

// ---------------------------------------------------------------------------
// HMMA GEMM fp16: C[M,N] = A[M,K] * B[N,K]^T, 64x64 warp tiles.
// 128 threads (4 warps, 2x2), 128x128 CTA tile, BK=32, 3-stage cp.async.
// (Unchanged from Round 16.)
// ---------------------------------------------------------------------------
#define BM 128
#define BN 128
#define BK 32
#define GT_B  (BM * BK * 2)        // 8192 bytes / tile
#define GSTG_B (2 * GT_B)          // 16384 bytes / stage (A, B)
#define GEMM_SMEM (3 * GSTG_B)     // 49152

__device__ __forceinline__ uint32_t gswz(int row, int c) {  // byte offset
    return (uint32_t)(row * BK + ((c ^ ((row >> 1) & 3)) << 3)) * 2;
}

template<int SPLIT>
__global__ __launch_bounds__(128, 2) void gemm_hmma(
    const __half* __restrict__ A, const __half* __restrict__ B,
    float* __restrict__ C, __half* __restrict__ Ch,
    int M, int N, int K)
{
    extern __shared__ __half dsm[];
    const uint32_t sb = smem_u32(dsm);
    const int tid = threadIdx.x;
    const int wid = tid >> 5;
    const int lid = tid & 31;
    const int warp_m = (wid & 1) * 64;
    const int warp_n = (wid >> 1) * 64;
    const int brow = blockIdx.y * BM;
    const int bcol = blockIdx.x * BN;

    float acc[4][8][4];
#pragma unroll
    for (int mf = 0; mf < 4; mf++)
#pragma unroll
        for (int nf = 0; nf < 8; nf++)
#pragma unroll
            for (int c = 0; c < 4; c++) acc[mf][nf][c] = 0.f;

    const int r0 = tid >> 2, c0 = tid & 3;
    uint32_t ow[4];
#pragma unroll
    for (int u = 0; u < 4; u++) ow[u] = gswz(r0 + 32 * u, c0);
    const int nk = K / BK;

    auto issue = [&](int kt, int st) {
        uint32_t d = sb + st * GSTG_B;
#pragma unroll
        for (int u = 0; u < 4; u++) {
            size_t gA = (size_t)(brow + r0 + 32 * u) * K + kt * BK + c0 * 8;
            size_t gB = (size_t)(bcol + r0 + 32 * u) * K + kt * BK + c0 * 8;
            cp16(d + ow[u],        A + gA);
            cp16(d + GT_B + ow[u], B + gB);
        }
    };

    issue(0, 0); CP_COMMIT();
    issue(1, 1); CP_COMMIT();

    const int a_r = lid & 15;
    const int a_c = lid >> 4;
    const int b_r = (lid & 7) + ((lid >> 4) & 1) * 8;
    const int b_c = (lid >> 3) & 1;

    for (int kt = 0; kt < nk; kt++) {
        int st = kt - (kt / 3) * 3;
        CP_WAIT(1);
        __syncthreads();
        if (kt + 2 < nk) { int k2 = kt + 2; issue(k2, k2 - (k2 / 3) * 3); }
        CP_COMMIT();

        uint32_t uA = sb + st * GSTG_B;
        uint32_t uB = uA + GT_B;

#pragma unroll
        for (int ks = 0; ks < 2; ks++) {
            uint32_t aa[4][4];
#pragma unroll
            for (int mf = 0; mf < 4; mf++) {
                uint32_t off = gswz(warp_m + mf * 16 + a_r, ks * 2 + a_c);
                ldsm_x4(aa[mf], uA + off);
            }
#pragma unroll
            for (int np = 0; np < 4; np++) {
                uint32_t bb[4];
                uint32_t off = gswz(warp_n + np * 16 + b_r, ks * 2 + b_c);
                ldsm_x4(bb, uB + off);
#pragma unroll
                for (int f = 0; f < 2; f++) {
                    int nf = 2 * np + f;
#pragma unroll
                    for (int mf = 0; mf < 4; mf++)
                        mma16816(acc[mf][nf], aa[mf], bb + 2 * f);
                }
            }
        }
    }

    const int er = lid >> 2;
    const int ec = (lid & 3) * 2;
#pragma unroll
    for (int mf = 0; mf < 4; mf++) {
#pragma unroll
        for (int nf = 0; nf < 8; nf++) {
            int row = brow + warp_m + mf * 16 + er;
            int col = bcol + warp_n + nf * 8 + ec;
            if (SPLIT) {
#pragma unroll
                for (int half = 0; half < 2; half++) {
                    size_t o = (size_t)(row + 8 * half) * N + col;
                    *(__half2*)(Ch + o) = __floats2half2_rn(acc[mf][nf][2 * half],
                                                            acc[mf][nf][2 * half + 1]);
                }
            } else {
                *(float2*)&C[(size_t)row * N + col] = make_float2(acc[mf][nf][0], acc[mf][nf][1]);
                *(float2*)&C[(size_t)(row + 8) * N + col] = make_float2(acc[mf][nf][2], acc[mf][nf][3]);
            }
        }
    }
}

// ---------------------------------------------------------------------------
// Flash attention (causal) fp16 HMMA: Br=128, 4 warps x 32 q-rows (128 thr).
// Bc=64 KV tiles, 3-stage cp.async, XOR swizzle. Scale folded into Q.
// Warp-tile 32x64 halves smem bytes/MMA vs 16x64.
// ---------------------------------------------------------------------------
#define FT_B   (64 * 64 * 2)        // 8192 bytes / KV sub-tile
#define FSTG_B (2 * FT_B)           // 16384 bytes / stage (K, V)
#define FA_SMEM (3 * FSTG_B)        // 49152 (Q staged through first 16KB)

__device__ __forceinline__ uint32_t fswz(int row, int c) {  // byte offset
    return (uint32_t)(row * 64 + ((c ^ (row & 7)) << 3)) * 2;
}

__global__ __launch_bounds__(128, 2) void flash_hmma(
    const __half* __restrict__ qkv,
    __half* __restrict__ att)
{
    extern __shared__ __half fsm[];
    const uint32_t sb = smem_u32(fsm);
    const int tid = threadIdx.x;
    const int wid = tid >> 5;
    const int lane = tid & 31;
    const int qt = (int)gridDim.x - 1 - (int)blockIdx.x;   // heavy first
    const int bh = blockIdx.y;
    const int b = bh >> 4;
    const int h = bh & 15;
    const int rowbase = b * SEQ;
    const int q0 = qt * 128;
    const int nkv = 2 * qt + 2;
    const int warp_m = wid * 32;

    // ---- stage Q (128 rows, 16KB in stage-0 space), read to regs, fold scale ----
#pragma unroll
    for (int i = 0; i < 8; i++) {
        int v = tid + i * 128;
        int r = v >> 3, c = v & 7;
        size_t g = (size_t)(rowbase + q0 + r) * QKV_N + h * HDIM + c * 8;
        cp16(sb + fswz(r, c), qkv + g);
    }
    CP_COMMIT(); CP_WAIT(0);
    __syncthreads();

    const __half2 sc2 = __half2(__float2half(0.125f), __float2half(0.125f));
    uint32_t Q[2][4][4];
#pragma unroll
    for (int mf = 0; mf < 2; mf++)
#pragma unroll
        for (int ks = 0; ks < 4; ks++) {
            uint32_t off = fswz(warp_m + mf * 16 + (lane & 15), ks * 2 + (lane >> 4));
            ldsm_x4(Q[mf][ks], sb + off);
#pragma unroll
            for (int i = 0; i < 4; i++) Q[mf][ks][i] = scale_h2(Q[mf][ks][i], sc2);
        }
    __syncthreads();

    float oacc[2][8][4];
#pragma unroll
    for (int mf = 0; mf < 2; mf++)
#pragma unroll
        for (int nd = 0; nd < 8; nd++)
#pragma unroll
            for (int c = 0; c < 4; c++) oacc[mf][nd][c] = 0.f;
    float m_[2][2] = {{-1e30f, -1e30f}, {-1e30f, -1e30f}};
    float l_[2][2] = {{0.f, 0.f}, {0.f, 0.f}};

    auto issue_kv = [&](int jt, int st) {
#pragma unroll
        for (int i = 0; i < 4; i++) {
            int v = tid + i * 128;
            int r = v >> 3, c = v & 7;
            size_t g = (size_t)(rowbase + jt * 64 + r) * QKV_N + h * HDIM + c * 8;
            uint32_t d = sb + st * FSTG_B + fswz(r, c);
            cp16(d,        qkv + g + DMODEL);       // K
            cp16(d + FT_B, qkv + g + 2 * DMODEL);   // V
        }
    };

    issue_kv(0, 0); CP_COMMIT();
    issue_kv(1, 1); CP_COMMIT();          // nkv >= 2 always

    const int k_r = (lane & 7) + ((lane >> 4) & 1) * 8;
    const int k_c = (lane >> 3) & 1;
    const int v_r = (lane & 7) + ((lane >> 3) & 1) * 8;
    const int v_c = (lane >> 4) & 1;
    const int row_in16 = lane >> 2;       // 0..7

    for (int jt = 0; jt < nkv; jt++) {
        int st = jt - (jt / 3) * 3;
        CP_WAIT(1);
        __syncthreads();
        if (jt + 2 < nkv) { int j2 = jt + 2; issue_kv(j2, j2 - (j2 / 3) * 3); }
        CP_COMMIT();

        const int kbase = jt * 64 - q0;   // k-tile base in q-tile local frame
        if (kbase > warp_m + 31) continue;  // fully above diagonal for this warp

        uint32_t uK = sb + st * FSTG_B;
        uint32_t uV = uK + FT_B;

        // ---- S = (Q*scale) K^T  (two 16-row m-frags) ----
        float sacc[2][8][4];
#pragma unroll
        for (int mf = 0; mf < 2; mf++)
#pragma unroll
            for (int nf = 0; nf < 8; nf++)
#pragma unroll
                for (int c = 0; c < 4; c++) sacc[mf][nf][c] = 0.f;

#pragma unroll
        for (int ks = 0; ks < 4; ks++) {
#pragma unroll
            for (int np = 0; np < 4; np++) {
                uint32_t kk[4];
                uint32_t off = fswz(np * 16 + k_r, ks * 2 + k_c);
                ldsm_x4(kk, uK + off);
#pragma unroll
                for (int f = 0; f < 2; f++) {
                    int nf = 2 * np + f;
#pragma unroll
                    for (int mf = 0; mf < 2; mf++)
                        mma16816(sacc[mf][nf], Q[mf][ks], kk + 2 * f);
                }
            }
        }

        // ---- causal mask (tiles straddling this warp's 32 rows) ----
        if (kbase + 63 > warp_m) {
#pragma unroll
            for (int mf = 0; mf < 2; mf++) {
                int qr0 = warp_m + mf * 16 + row_in16;
                int qr1 = qr0 + 8;
#pragma unroll
                for (int nf = 0; nf < 8; nf++) {
                    int col = kbase + nf * 8 + (lane & 3) * 2;
                    sacc[mf][nf][0] = (col     <= qr0) ? sacc[mf][nf][0] : -1e30f;
                    sacc[mf][nf][1] = (col + 1 <= qr0) ? sacc[mf][nf][1] : -1e30f;
                    sacc[mf][nf][2] = (col     <= qr1) ? sacc[mf][nf][2] : -1e30f;
                    sacc[mf][nf][3] = (col + 1 <= qr1) ? sacc[mf][nf][3] : -1e30f;
                }
            }
        }

        // ---- online softmax (per m-frag, rows qr0 / qr1) ----
#pragma unroll
        for (int mf = 0; mf < 2; mf++) {
            float mx0 = -1e30f, mx1 = -1e30f;
#pragma unroll
            for (int nf = 0; nf < 8; nf++) {
                mx0 = fmaxf(mx0, fmaxf(sacc[mf][nf][0], sacc[mf][nf][1]));
                mx1 = fmaxf(mx1, fmaxf(sacc[mf][nf][2], sacc[mf][nf][3]));
            }
            mx0 = fmaxf(mx0, __shfl_xor_sync(0xffffffffu, mx0, 1));
            mx0 = fmaxf(mx0, __shfl_xor_sync(0xffffffffu, mx0, 2));
            mx1 = fmaxf(mx1, __shfl_xor_sync(0xffffffffu, mx1, 1));
            mx1 = fmaxf(mx1, __shfl_xor_sync(0xffffffffu, mx1, 2));
            float mn0 = fmaxf(m_[mf][0], mx0), mn1 = fmaxf(m_[mf][1], mx1);
            float al0 = __expf(m_[mf][0] - mn0), al1 = __expf(m_[mf][1] - mn1);
            float s0 = 0.f, s1 = 0.f;
#pragma unroll
            for (int nf = 0; nf < 8; nf++) {
                sacc[mf][nf][0] = __expf(sacc[mf][nf][0] - mn0); s0 += sacc[mf][nf][0];
                sacc[mf][nf][1] = __expf(sacc[mf][nf][1] - mn0); s0 += sacc[mf][nf][1];
                sacc[mf][nf][2] = __expf(sacc[mf][nf][2] - mn1); s1 += sacc[mf][nf][2];
                sacc[mf][nf][3] = __expf(sacc[mf][nf][3] - mn1); s1 += sacc[mf][nf][3];
            }
            s0 += __shfl_xor_sync(0xffffffffu, s0, 1);
            s0 += __shfl_xor_sync(0xffffffffu, s0, 2);
            s1 += __shfl_xor_sync(0xffffffffu, s1, 1);
            s1 += __shfl_xor_sync(0xffffffffu, s1, 2);
            l_[mf][0] = l_[mf][0] * al0 + s0; m_[mf][0] = mn0;
            l_[mf][1] = l_[mf][1] * al1 + s1; m_[mf][1] = mn1;
#pragma unroll
            for (int nd = 0; nd < 8; nd++) {
                oacc[mf][nd][0] *= al0; oacc[mf][nd][1] *= al0;
                oacc[mf][nd][2] *= al1; oacc[mf][nd][3] *= al1;
            }
        }

        // ---- O += P V ----
#pragma unroll
        for (int kb = 0; kb < 4; kb++) {
            uint32_t pa[2][4];
#pragma unroll
            for (int mf = 0; mf < 2; mf++) {
                pa[mf][0] = pack_h2(sacc[mf][2 * kb][0],     sacc[mf][2 * kb][1]);
                pa[mf][1] = pack_h2(sacc[mf][2 * kb][2],     sacc[mf][2 * kb][3]);
                pa[mf][2] = pack_h2(sacc[mf][2 * kb + 1][0], sacc[mf][2 * kb + 1][1]);
                pa[mf][3] = pack_h2(sacc[mf][2 * kb + 1][2], sacc[mf][2 * kb + 1][3]);
            }
#pragma unroll
            for (int ndp = 0; ndp < 4; ndp++) {
                uint32_t vv[4];
                uint32_t off = fswz(kb * 16 + v_r, ndp * 2 + v_c);
                ldsm_x4_t(vv, uV + off);
#pragma unroll
                for (int f = 0; f < 2; f++) {
                    int nd = 2 * ndp + f;
#pragma unroll
                    for (int mf = 0; mf < 2; mf++)
                        mma16816(oacc[mf][nd], pa[mf], vv + 2 * f);
                }
            }
        }
    }

    // ---- epilogue: normalize, write fp16 ----
#pragma unroll
    for (int mf = 0; mf < 2; mf++) {
        float inv0 = 1.f / l_[mf][0], inv1 = 1.f / l_[mf][1];
        int grow0 = rowbase + q0 + warp_m + mf * 16 + row_in16;
#pragma unroll
        for (int nd = 0; nd < 8; nd++) {
            int col = h * HDIM + nd * 8 + (lane & 3) * 2;
#pragma unroll
            for (int half = 0; half < 2; half++) {
                float v0 = oacc[mf][nd][2 * half]     * (half ? inv1 : inv0);
                float v1 = oacc[mf][nd][2 * half + 1] * (half ? inv1 : inv0);
                size_t o = (size_t)(grow0 + 8 * half) * DMODEL + col;
                *(__half2*)(att + o) = __floats2half2_rn(v0, v1);
            }
        }
    }
}

// ---------------------------------------------------------------------------
// Launch
// ---------------------------------------------------------------------------
extern "C" void kernel_launch(void* const* d_in, const int* in_sizes, int n_in,
                              void* d_out, int out_size)
{
    (void)in_sizes; (void)n_in; (void)out_size;
    const float* x     = (const float*)d_in[0];
    const float* W_qkv = (const float*)d_in[1];
    const float* W_out = (const float*)d_in[2];
    float* out = (float*)d_out;

    __half *xf, *wq, *wo, *qkv, *att;
    cudaGetSymbolAddress((void**)&xf, g_x);
    cudaGetSymbolAddress((void**)&wq, g_wq);
    cudaGetSymbolAddress((void**)&wo, g_wo);
    cudaGetSymbolAddress((void**)&qkv, g_qkv);
    cudaGetSymbolAddress((void**)&att, g_att);

    cudaFuncSetAttribute((const void*)gemm_hmma<1>, cudaFuncAttributeMaxDynamicSharedMemorySize, GEMM_SMEM);
    cudaFuncSetAttribute((const void*)gemm_hmma<0>, cudaFuncAttributeMaxDynamicSharedMemorySize, GEMM_SMEM);
    cudaFuncSetAttribute((const void*)flash_hmma, cudaFuncAttributeMaxDynamicSharedMemorySize, FA_SMEM);

    cvt_all<<<(NX4 + NQ4 + NO4 + 255) / 256, 256>>>(x, W_qkv, W_out, xf, wq, wo);

    // 1) QKV projection -> fp16
    gemm_hmma<1><<<dim3(QKV_N / BN, MROWS / BM), 128, GEMM_SMEM>>>(
        xf, wq, nullptr, qkv, MROWS, QKV_N, DMODEL);

    // 2) causal flash attention (Br=128, 32-row warp tiles) -> fp16
    flash_hmma<<<dim3(SEQ / 128, BATCH * NHEADS), 128, FA_SMEM>>>(qkv, att);

    // 3) output projection -> fp32
    gemm_hmma<0><<<dim3(DMODEL / BN, MROWS / BM), 128, GEMM_SMEM>>>(
        att, wo, out, nullptr, MROWS, DMODEL, DMODEL);
}